// round 11
// baseline (speedup 1.0000x reference)
#include <cuda_runtime.h>

// IF spiking neuron, T=4 timesteps — FINAL.
//
// Roofline verdict after an 8-config sweep (MLP 4/8, .cs hints, persistent
// one-wave, TPB 256/512/1024, interleaved vs batched STG, 128-bit vs 256-bit
// accesses): all configs within 35.6-36.8us kernel time. Mandatory traffic is
// 134MB read + 134MB write (no reuse, fp32 required); at 35.6us that is
// ~7.54 TB/s effective = 94% of HBM3e spec — the hardware ceiling for a 1:1
// read/write streaming mix. ncu's DRAM% (~76) undercounts due to dirty-line
// L2 residency at measurement end.
//
// Selected config (best kernel time 35.58us AND best DRAM% 76.1):
//   TPB=512, one float4 column per thread, 4 front-batched independent
//   LDG.128 (MLP=4), full register-resident T-scan, then 4 back-to-back
//   STG.128 as a write burst.

#define T_STEPS 4
#define TPB 512

__global__ __launch_bounds__(TPB) void if_kernel(
    const float4* __restrict__ x,
    float4* __restrict__ out,
    const float* __restrict__ thresh_p,
    int n_vec_per_t)   // (B*C*H*W)/4 = 2,097,152
{
    int i = blockIdx.x * blockDim.x + threadIdx.x;
    if (i >= n_vec_per_t) return;

    const float th = __ldg(thresh_p);
    const float half_th = 0.5f * th;

    // Front-batch all 4 timestep loads (independent addresses -> MLP=4).
    float4 x0 = x[0 * (size_t)n_vec_per_t + i];
    float4 x1 = x[1 * (size_t)n_vec_per_t + i];
    float4 x2 = x[2 * (size_t)n_vec_per_t + i];
    float4 x3 = x[3 * (size_t)n_vec_per_t + i];

    float4 m = make_float4(half_th, half_th, half_th, half_th);
    float4 s0, s1, s2, s3;

    // t = 0
    m.x += x0.x; s0.x = (m.x >= th) ? th : 0.0f; m.x -= s0.x;
    m.y += x0.y; s0.y = (m.y >= th) ? th : 0.0f; m.y -= s0.y;
    m.z += x0.z; s0.z = (m.z >= th) ? th : 0.0f; m.z -= s0.z;
    m.w += x0.w; s0.w = (m.w >= th) ? th : 0.0f; m.w -= s0.w;

    // t = 1
    m.x += x1.x; s1.x = (m.x >= th) ? th : 0.0f; m.x -= s1.x;
    m.y += x1.y; s1.y = (m.y >= th) ? th : 0.0f; m.y -= s1.y;
    m.z += x1.z; s1.z = (m.z >= th) ? th : 0.0f; m.z -= s1.z;
    m.w += x1.w; s1.w = (m.w >= th) ? th : 0.0f; m.w -= s1.w;

    // t = 2
    m.x += x2.x; s2.x = (m.x >= th) ? th : 0.0f; m.x -= s2.x;
    m.y += x2.y; s2.y = (m.y >= th) ? th : 0.0f; m.y -= s2.y;
    m.z += x2.z; s2.z = (m.z >= th) ? th : 0.0f; m.z -= s2.z;
    m.w += x2.w; s2.w = (m.w >= th) ? th : 0.0f; m.w -= s2.w;

    // t = 3 (mem not needed afterwards)
    m.x += x3.x; s3.x = (m.x >= th) ? th : 0.0f;
    m.y += x3.y; s3.y = (m.y >= th) ? th : 0.0f;
    m.z += x3.z; s3.z = (m.z >= th) ? th : 0.0f;
    m.w += x3.w; s3.w = (m.w >= th) ? th : 0.0f;

    // Back-to-back write burst: 4 consecutive STG.128 per thread.
    out[0 * (size_t)n_vec_per_t + i] = s0;
    out[1 * (size_t)n_vec_per_t + i] = s1;
    out[2 * (size_t)n_vec_per_t + i] = s2;
    out[3 * (size_t)n_vec_per_t + i] = s3;
}

extern "C" void kernel_launch(void* const* d_in, const int* in_sizes, int n_in,
                              void* d_out, int out_size) {
    const float* x = (const float*)d_in[0];
    const float* thresh = (const float*)d_in[1];

    int n_total = in_sizes[0];            // T * B * C * H * W = 33,554,432
    int n_per_t = n_total / T_STEPS;      // 8,388,608
    int n_vec_per_t = n_per_t / 4;        // 2,097,152 float4 columns

    int blocks = (n_vec_per_t + TPB - 1) / TPB;  // 4096

    if_kernel<<<blocks, TPB>>>(
        (const float4*)x, (float4*)d_out, thresh, n_vec_per_t);
}

// round 12
// speedup vs baseline: 1.0088x; 1.0088x over previous
#include <cuda_runtime.h>

// IF spiking neuron, T=4 timesteps. HBM streaming ~7.5 TB/s effective.
// Round-12: R7 body (TPB=512, batched stores) with __stwt write-through
// stores — hypothesis: smooth the write stream into the DRAM scheduler
// instead of back-loading it via lazy dirty-line writeback (ncu shows
// dram__cycles_active only 75% and ~54MB of writes parked in L2 at end).

#define T_STEPS 4
#define TPB 512

__global__ __launch_bounds__(TPB) void if_kernel(
    const float4* __restrict__ x,
    float4* __restrict__ out,
    const float* __restrict__ thresh_p,
    int n_vec_per_t)   // (B*C*H*W)/4 = 2,097,152
{
    int i = blockIdx.x * blockDim.x + threadIdx.x;
    if (i >= n_vec_per_t) return;

    const float th = __ldg(thresh_p);
    const float half_th = 0.5f * th;

    // Front-batch all 4 timestep loads (independent addresses -> MLP=4).
    float4 x0 = x[0 * (size_t)n_vec_per_t + i];
    float4 x1 = x[1 * (size_t)n_vec_per_t + i];
    float4 x2 = x[2 * (size_t)n_vec_per_t + i];
    float4 x3 = x[3 * (size_t)n_vec_per_t + i];

    float4 m = make_float4(half_th, half_th, half_th, half_th);
    float4 s0, s1, s2, s3;

    // t = 0
    m.x += x0.x; s0.x = (m.x >= th) ? th : 0.0f; m.x -= s0.x;
    m.y += x0.y; s0.y = (m.y >= th) ? th : 0.0f; m.y -= s0.y;
    m.z += x0.z; s0.z = (m.z >= th) ? th : 0.0f; m.z -= s0.z;
    m.w += x0.w; s0.w = (m.w >= th) ? th : 0.0f; m.w -= s0.w;

    // t = 1
    m.x += x1.x; s1.x = (m.x >= th) ? th : 0.0f; m.x -= s1.x;
    m.y += x1.y; s1.y = (m.y >= th) ? th : 0.0f; m.y -= s1.y;
    m.z += x1.z; s1.z = (m.z >= th) ? th : 0.0f; m.z -= s1.z;
    m.w += x1.w; s1.w = (m.w >= th) ? th : 0.0f; m.w -= s1.w;

    // t = 2
    m.x += x2.x; s2.x = (m.x >= th) ? th : 0.0f; m.x -= s2.x;
    m.y += x2.y; s2.y = (m.y >= th) ? th : 0.0f; m.y -= s2.y;
    m.z += x2.z; s2.z = (m.z >= th) ? th : 0.0f; m.z -= s2.z;
    m.w += x2.w; s2.w = (m.w >= th) ? th : 0.0f; m.w -= s2.w;

    // t = 3 (mem not needed afterwards)
    m.x += x3.x; s3.x = (m.x >= th) ? th : 0.0f;
    m.y += x3.y; s3.y = (m.y >= th) ? th : 0.0f;
    m.z += x3.z; s3.z = (m.z >= th) ? th : 0.0f;
    m.w += x3.w; s3.w = (m.w >= th) ? th : 0.0f;

    // Write-through store burst: push writes to DRAM immediately.
    __stwt(&out[0 * (size_t)n_vec_per_t + i], s0);
    __stwt(&out[1 * (size_t)n_vec_per_t + i], s1);
    __stwt(&out[2 * (size_t)n_vec_per_t + i], s2);
    __stwt(&out[3 * (size_t)n_vec_per_t + i], s3);
}

extern "C" void kernel_launch(void* const* d_in, const int* in_sizes, int n_in,
                              void* d_out, int out_size) {
    const float* x = (const float*)d_in[0];
    const float* thresh = (const float*)d_in[1];

    int n_total = in_sizes[0];            // T * B * C * H * W = 33,554,432
    int n_per_t = n_total / T_STEPS;      // 8,388,608
    int n_vec_per_t = n_per_t / 4;        // 2,097,152 float4 columns

    int blocks = (n_vec_per_t + TPB - 1) / TPB;  // 4096

    if_kernel<<<blocks, TPB>>>(
        (const float4*)x, (float4*)d_out, thresh, n_vec_per_t);
}